// round 17
// baseline (speedup 1.0000x reference)
#include <cuda_runtime.h>

#define B_TOTAL 16384
#define NSTEPS  196

// Scratch (allocation-free: __device__ globals)
__device__ float g_xT[784 * B_TOTAL];    // transposed, PRE-HALVED input: [pixel][batch]
__device__ float g_w1T[NSTEPS * 4 * 20]; // fc1 weights: [(s*4+w)*20 + o]

// ---------------------------------------------------------------------------
// Prep kernel: float4 transpose of x -> g_xT = 0.5*x^T, plus fc1_w relayout.
// ---------------------------------------------------------------------------
__global__ void prep_kernel(const float* __restrict__ x, const float* __restrict__ fc1_w) {
    if (blockIdx.y == 25) {
        int t = threadIdx.y * 8 + threadIdx.x;
        int idx = blockIdx.x * 256 + t;
        if (idx < 784 * 20) {
            int p = idx / 20, o = idx % 20;
            g_w1T[idx] = fc1_w[o * 784 + p];
        }
        return;
    }
    __shared__ float tile[32][33];
    const int bBase = blockIdx.x * 32;
    const int pBase = blockIdx.y * 32;
    const int tx = threadIdx.x, ty = threadIdx.y;
    int p0 = pBase + tx * 4;
    float4 v = make_float4(0.f, 0.f, 0.f, 0.f);
    if (p0 < 784) v = *(const float4*)(x + (bBase + ty) * 784 + p0);
    tile[tx * 4 + 0][ty] = 0.5f * v.x;
    tile[tx * 4 + 1][ty] = 0.5f * v.y;
    tile[tx * 4 + 2][ty] = 0.5f * v.z;
    tile[tx * 4 + 3][ty] = 0.5f * v.w;
    __syncthreads();
    int p = pBase + ty;
    if (p < 784) {
        float4 w = make_float4(tile[ty][tx * 4 + 0], tile[ty][tx * 4 + 1],
                               tile[ty][tx * 4 + 2], tile[ty][tx * 4 + 3]);
        *(float4*)(g_xT + p * B_TOTAL + bBase + tx * 4) = w;
    }
}

// ---------------------------------------------------------------------------
// Apply U = [[u, v],[conj(v), -conj(u)]] on wire with stride S (16 amps).
// ---------------------------------------------------------------------------
template<int S>
__device__ __forceinline__ void applyUV(float* Sr, float* Si,
    float ur, float ui, float vr, float vi)
{
    #pragma unroll
    for (int g = 0; g < 8; g++) {
        int i0 = ((g & ~(S - 1)) << 1) | (g & (S - 1));
        int i1 = i0 + S;
        float x0r = Sr[i0], x0i = Si[i0], x1r = Sr[i1], x1i = Si[i1];
        Sr[i0] = ur * x0r - ui * x0i + vr * x1r - vi * x1i;
        Si[i0] = ur * x0i + ui * x0r + vr * x1i + vi * x1r;
        Sr[i1] = vr * x0r + vi * x0i - ur * x1r - ui * x1i;
        Si[i1] = vr * x0i - vi * x0r - ur * x1i + ui * x1r;
    }
}

template<int S>
__device__ __forceinline__ float xdot(const float* Sr, const float* Si) {
    float ar = 0.f, ai = 0.f;
    #pragma unroll
    for (int g = 0; g < 8; g++) {
        int i0 = ((g & ~(S - 1)) << 1) | (g & (S - 1));
        int i1 = i0 + S;
        ar += Sr[i0] * Sr[i1];
        ai += Si[i0] * Si[i1];
    }
    return ar + ai;
}

// Quaternion chain: RZ(a4)RY(a3)RZ(a2)RY(a1)RZ(a0) * G, G=[gA,gB;gB,-gA].
__device__ __forceinline__ void chain5(const float* a, float gA, float gB,
    float& ur, float& ui, float& vr, float& vi)
{
    float c0a = __cosf(a[0]), s0a = __sinf(a[0]);
    float c1a = __cosf(a[1]), s1a = __sinf(a[1]);
    float c2a = __cosf(a[2]), s2a = __sinf(a[2]);
    float c3a = __cosf(a[3]), s3a = __sinf(a[3]);
    float c4a = __cosf(a[4]), s4a = __sinf(a[4]);
    float qw = c4a * c3a, qx = -s4a * s3a, qy = c4a * s3a, qz = s4a * c3a;
    float tw = qw * c2a - qz * s2a;
    float tx = qx * c2a + qy * s2a;
    float ty = qy * c2a - qx * s2a;
    float tz = qz * c2a + qw * s2a;
    qw = tw * c1a - ty * s1a;
    qx = tx * c1a - tz * s1a;
    qy = ty * c1a + tw * s1a;
    qz = tz * c1a + tx * s1a;
    tw = qw * c0a - qz * s0a;
    tx = qx * c0a + qy * s0a;
    ty = qy * c0a - qx * s0a;
    tz = qz * c0a + qw * s0a;
    ur = tw * gA - ty * gB;
    ui = -(tz * gA + tx * gB);
    vr = tw * gB + ty * gA;
    vi = tx * gA - tz * gB;
}

// ---------------------------------------------------------------------------
// Main kernel: R9 math, software-pipelined:
//   gates(s+1) built during step s's applies; fc1(s-1) during step s;
//   angles(s+2) prefetched; pointer-increment addressing (no per-load IMADs).
// ---------------------------------------------------------------------------
__global__ __launch_bounds__(128, 1) void quanv_kernel(
    const float* __restrict__ crz_p, const float* __restrict__ ry_p,
    const float* __restrict__ fc1_b, const float* __restrict__ fc2_w,
    const float* __restrict__ fc2_b, float* __restrict__ out)
{
    const int b = blockIdx.x * 128 + threadIdx.x;
    const float RS = 0.7071067811865476f;

    // CRZ phases
    const float th = __ldg(crz_p);
    const float c1 = __cosf(0.5f * th), s1 = __sinf(0.5f * th);
    const float c2 = __cosf(th),        s2 = __sinf(th);
    const float c4 = __cosf(2.0f * th), s4 = __sinf(2.0f * th);

    const float ryt = __ldg(ry_p);
    const float cTH  = __cosf(ryt);
    const float s2TH = 2.0f * __sinf(ryt);
    const float chh = __cosf(0.5f * ryt), shh = __sinf(0.5f * ryt);
    const float gAf = RS * (chh + shh), gBf = RS * (chh - shh);  // H*Ry entries

    // State |0000>
    float Sr[16], Si[16];
    #pragma unroll
    for (int n = 0; n < 16; n++) { Sr[n] = 0.f; Si[n] = 0.f; }
    Sr[0] = 1.f;

    // Fused fc1 accumulators
    float h1[20];
    #pragma unroll
    for (int o = 0; o < 20; o++) h1[o] = __ldg(&fc1_b[o]);

    const float* nb = g_xT + b;

    // ---- angles(0) (window (0,0), full), gates(0) with G = H ----
    float A[16];
    #pragma unroll
    for (int k = 0; k < 16; k++)
        A[k] = nb[((k >> 2) * 28 + (k & 3)) * B_TOTAL];
    nb += 2 * B_TOTAL;

    float Gc[16];   // gates for current step: [w*4 + {ur,ui,vr,vi}]
    chain5(A,      RS, RS, Gc[0], Gc[1], Gc[2],  Gc[3]);
    chain5(A + 5,  RS, RS, Gc[4], Gc[5], Gc[6],  Gc[7]);
    chain5(A + 10, RS, RS, Gc[8], Gc[9], Gc[10], Gc[11]);
    {
        float c0a = __cosf(A[15]), s0a = __sinf(A[15]);
        Gc[12] = c0a * RS; Gc[13] = -s0a * RS;
        Gc[14] = c0a * RS; Gc[15] = -s0a * RS;
    }

    // ---- angles(1) (window (0,1), full) ----
    #pragma unroll
    for (int k = 0; k < 16; k++)
        A[k] = nb[((k >> 2) * 28 + (k & 3)) * B_TOTAL];
    nb += 2 * B_TOTAL;

    float evP[4];                 // ev of previous step (consumed next iter)
    int nwi = 0, nwj = 2;         // window coords of the NEXT load (s+2)

    #pragma unroll 1
    for (int s = 0; s < NSTEPS; s++) {
        // ---- prefetch angles(s+2): uniform window-type branches ----
        float An[16];
        if (s >= NSTEPS - 2) {
            #pragma unroll
            for (int k = 0; k < 16; k++) An[k] = 0.f;
        } else if (nwj != 13 && nwi != 13) {        // full 4x4 (majority)
            #pragma unroll
            for (int k = 0; k < 16; k++)
                An[k] = nb[((k >> 2) * 28 + (k & 3)) * B_TOTAL];
            if (nwj == 13) { nb += 30 * B_TOTAL; nwj = 0; nwi++; }
            else           { nb += 2 * B_TOTAL;  nwj++; }
        } else if (nwj == 13 && nwi == 13) {        // corner 2x2
            #pragma unroll
            for (int k = 0; k < 16; k++)
                An[k] = (k < 4) ? nb[((k >> 1) * 28 + (k & 1)) * B_TOTAL] : 0.f;
            nb += 30 * B_TOTAL; nwj = 0; nwi++;
        } else if (nwj == 13) {                     // right edge 4x2
            #pragma unroll
            for (int k = 0; k < 16; k++)
                An[k] = (k < 8) ? nb[((k >> 1) * 28 + (k & 1)) * B_TOTAL] : 0.f;
            nb += 30 * B_TOTAL; nwj = 0; nwi++;
        } else {                                    // bottom edge 2x4
            #pragma unroll
            for (int k = 0; k < 16; k++)
                An[k] = (k < 8) ? nb[((k >> 2) * 28 + (k & 3)) * B_TOTAL] : 0.f;
            nb += 2 * B_TOTAL; nwj++;
        }

        // ---- fc1 for step s-1 (pipelined; overlaps this step's spine) ----
        if (s > 0) {
            const float4* w4 = (const float4*)(g_w1T + (s - 1) * 80);
            #pragma unroll
            for (int w = 0; w < 4; w++) {
                #pragma unroll
                for (int q = 0; q < 5; q++) {
                    float4 ww = __ldg(&w4[w * 5 + q]);
                    h1[q * 4 + 0] += evP[w] * ww.x;
                    h1[q * 4 + 1] += evP[w] * ww.y;
                    h1[q * 4 + 2] += evP[w] * ww.z;
                    h1[q * 4 + 3] += evP[w] * ww.w;
                }
            }
        }

        // ---- build gates(s+1) from A (independent of state; fills stalls) ----
        float Gn[16];
        chain5(A,      gAf, gBf, Gn[0], Gn[1], Gn[2],  Gn[3]);
        chain5(A + 5,  gAf, gBf, Gn[4], Gn[5], Gn[6],  Gn[7]);
        chain5(A + 10, gAf, gBf, Gn[8], Gn[9], Gn[10], Gn[11]);
        {
            float c0a = __cosf(A[15]), s0a = __sinf(A[15]);
            Gn[12] = c0a * gAf; Gn[13] = -s0a * gAf;
            Gn[14] = c0a * gBf; Gn[15] = -s0a * gBf;
        }

        // ---- apply gates(s) (serial spine) ----
        applyUV<8>(Sr, Si, Gc[0],  Gc[1],  Gc[2],  Gc[3]);
        applyUV<4>(Sr, Si, Gc[4],  Gc[5],  Gc[6],  Gc[7]);
        applyUV<2>(Sr, Si, Gc[8],  Gc[9],  Gc[10], Gc[11]);
        applyUV<1>(Sr, Si, Gc[12], Gc[13], Gc[14], Gc[15]);

        // ---- probs + Z butterfly (pre-CRZ; CRZ-invariant) ----
        float p[16];
        #pragma unroll
        for (int n = 0; n < 16; n++) p[n] = Sr[n] * Sr[n] + Si[n] * Si[n];
        float t8[8], z3 = 0.f;
        #pragma unroll
        for (int g = 0; g < 8; g++) { t8[g] = p[2*g] + p[2*g+1]; z3 += p[2*g] - p[2*g+1]; }
        float t4[4], z2 = 0.f;
        #pragma unroll
        for (int g = 0; g < 4; g++) { t4[g] = t8[2*g] + t8[2*g+1]; z2 += t8[2*g] - t8[2*g+1]; }
        float t2[2], z1 = 0.f;
        #pragma unroll
        for (int g = 0; g < 2; g++) { t2[g] = t4[2*g] + t4[2*g+1]; z1 += t4[2*g] - t4[2*g+1]; }
        float z0 = t2[0] - t2[1];

        // ---- CRZ diagonal: sgn {0,-1,-1,0,-1,-2,0,1,-1,0,-2,1,0,1,1,4} ----
        #define CRZM(n, CR, CI) { float r_ = Sr[n]*(CR) - Si[n]*(CI); \
                                  Si[n]    = Sr[n]*(CI) + Si[n]*(CR); Sr[n] = r_; }
        CRZM(1,  c1, -s1)  CRZM(2,  c1, -s1)  CRZM(4,  c1, -s1)
        CRZM(5,  c2, -s2)  CRZM(7,  c1,  s1)  CRZM(8,  c1, -s1)
        CRZM(10, c2, -s2)  CRZM(11, c1,  s1)  CRZM(13, c1,  s1)
        CRZM(14, c1,  s1)  CRZM(15, c4,  s4)
        #undef CRZM

        // ---- X expectations + rotated observables ----
        float x0 = xdot<8>(Sr, Si), x1 = xdot<4>(Sr, Si);
        float x2 = xdot<2>(Sr, Si), x3 = xdot<1>(Sr, Si);
        evP[0] = cTH * z0 - s2TH * x0;
        evP[1] = cTH * z1 - s2TH * x1;
        evP[2] = cTH * z2 - s2TH * x2;
        evP[3] = cTH * z3 - s2TH * x3;

        // ---- rotate pipeline registers ----
        #pragma unroll
        for (int k = 0; k < 16; k++) { Gc[k] = Gn[k]; A[k] = An[k]; }
    }

    // ---- final fc1 (step NSTEPS-1) ----
    {
        const float4* w4 = (const float4*)(g_w1T + (NSTEPS - 1) * 80);
        #pragma unroll
        for (int w = 0; w < 4; w++) {
            #pragma unroll
            for (int q = 0; q < 5; q++) {
                float4 ww = __ldg(&w4[w * 5 + q]);
                h1[q * 4 + 0] += evP[w] * ww.x;
                h1[q * 4 + 1] += evP[w] * ww.y;
                h1[q * 4 + 2] += evP[w] * ww.z;
                h1[q * 4 + 3] += evP[w] * ww.w;
            }
        }
    }

    // ---- leaky relu + fc2 ----
    float o0 = __ldg(&fc2_b[0]), o1 = __ldg(&fc2_b[1]);
    #pragma unroll
    for (int o = 0; o < 20; o++) {
        float hv = h1[o];
        hv = (hv > 0.f) ? hv : 0.1f * hv;
        o0 += hv * __ldg(&fc2_w[o]);
        o1 += hv * __ldg(&fc2_w[20 + o]);
    }
    out[b * 2 + 0] = o0;
    out[b * 2 + 1] = o1;
}

// ---------------------------------------------------------------------------
// Launch
// ---------------------------------------------------------------------------
extern "C" void kernel_launch(void* const* d_in, const int* in_sizes, int n_in,
                              void* d_out, int out_size) {
    const float* x      = (const float*)d_in[0];
    const float* crz_t  = (const float*)d_in[1];
    const float* ry_t   = (const float*)d_in[2];
    const float* fc1_w  = (const float*)d_in[3];
    const float* fc1_b  = (const float*)d_in[4];
    const float* fc2_w  = (const float*)d_in[5];
    const float* fc2_b  = (const float*)d_in[6];
    float* out = (float*)d_out;

    dim3 tbP(8, 32);
    dim3 tgP(B_TOTAL / 32, 26);
    prep_kernel<<<tgP, tbP>>>(x, fc1_w);

    quanv_kernel<<<B_TOTAL / 128, 128>>>(crz_t, ry_t, fc1_b, fc2_w, fc2_b, out);
}